// round 1
// baseline (speedup 1.0000x reference)
#include <cuda_runtime.h>
#include <cuda_bf16.h>
#include <math.h>
#include <float.h>

#define BB 8
#define TT 4096
#define DD 3
#define HH 128
#define NBLK 6
#define KK 20
#define BT (BB*TT)   // 32768

// ---------------- scratch (device globals; no allocation) ----------------
__device__ float g_net[BT * HH];   // 16 MB
__device__ float g_att[BT * HH];   // 16 MB
__device__ int   g_idx[BT * KK];
__device__ float g_dis[BT * KK];

// ======================= KNN ============================================
// grid (32, 8), block 128: one thread per query token. Register top-20.
__global__ __launch_bounds__(128) void knn_kernel(const float* __restrict__ p)
{
    const int b  = blockIdx.y;
    const int tt = blockIdx.x * 128 + threadIdx.x;
    const float* pb = p + (size_t)b * TT * 3;

    const float qx = pb[tt*3 + 0];
    const float qy = pb[tt*3 + 1];
    const float qz = pb[tt*3 + 2];
    const float sqq = (qx*qx + qy*qy) + qz*qz;

    float bd[KK];
    int   bi[KK];
#pragma unroll
    for (int k = 0; k < KK; ++k) { bd[k] = FLT_MAX; bi[k] = 0; }

    __shared__ float4 sp[1024];   // x,y,z,|.|^2

    for (int s0 = 0; s0 < TT; s0 += 1024) {
        __syncthreads();
        for (int l = threadIdx.x; l < 1024; l += 128) {
            const float* q = pb + (size_t)(s0 + l) * 3;
            float x = q[0], y = q[1], z = q[2];
            sp[l] = make_float4(x, y, z, (x*x + y*y) + z*z);
        }
        __syncthreads();
#pragma unroll 4
        for (int l = 0; l < 1024; ++l) {
            float4 v = sp[l];
            float dot = qx*v.x + qy*v.y + qz*v.z;
            float d2  = sqq + v.w - 2.0f * dot;
            if (d2 < bd[KK-1]) {
                bd[KK-1] = d2; bi[KK-1] = s0 + l;
#pragma unroll
                for (int q2 = KK-1; q2 > 0; --q2) {
                    if (bd[q2] < bd[q2-1]) {
                        float td = bd[q2]; bd[q2] = bd[q2-1]; bd[q2-1] = td;
                        int   ti = bi[q2]; bi[q2] = bi[q2-1]; bi[q2-1] = ti;
                    }
                }
            }
        }
    }

    const size_t o = ((size_t)b * TT + tt) * KK;
#pragma unroll
    for (int k = 0; k < KK; ++k) {
        g_idx[o + k] = bi[k];
        g_dis[o + k] = sqrtf(fmaxf(bd[k], 1e-12f));
    }
}

// ======================= positional encoding ============================
// net[t,h] = p[t]·W_pos[:,h] + b_pos[h]
__global__ __launch_bounds__(256) void pos_kernel(const float* __restrict__ p,
                                                  const float* __restrict__ W_pos,
                                                  const float* __restrict__ b_pos)
{
    int gid = blockIdx.x * 256 + threadIdx.x;   // < BT*HH
    int t = gid >> 7;
    int h = gid & 127;
    const float* pp = p + (size_t)t * 3;
    float v = b_pos[h];
    v = fmaf(pp[0], W_pos[h],        v);
    v = fmaf(pp[1], W_pos[HH + h],   v);
    v = fmaf(pp[2], W_pos[2*HH + h], v);
    g_net[gid] = v;
}

// ======================= attention (gather + softmax) ===================
// one warp per token; writes attv (pre-Wo) to g_att.
__global__ __launch_bounds__(256) void attn_kernel(const float* __restrict__ p,
                                                   const float* __restrict__ wc,
                                                   const float* __restrict__ bc)
{
    const int warp = threadIdx.x >> 5;
    const int lane = threadIdx.x & 31;
    const int t  = blockIdx.x * 8 + warp;      // 0..BT-1
    const int b  = t >> 12;
    const int tt = t & (TT - 1);
    const float* pb = p + (size_t)b * TT * 3;

    const float q0 = pb[tt*3+0], q1 = pb[tt*3+1], q2 = pb[tt*3+2];
    const float w0 = wc[0], w1 = wc[1], w2 = wc[2], w3 = wc[3];
    const float w4 = wc[4], w5 = wc[5], w6 = wc[6], bcv = bc[0];

    float s = -FLT_MAX;
    int   j = 0;
    if (lane < KK) {
        size_t o = (size_t)t * KK + lane;
        j = g_idx[o];
        float d = g_dis[o];
        const float* px = pb + (size_t)j * 3;
        s = bcv;
        s = fmaf(w0, d,     s);
        s = fmaf(w1, px[0], s);
        s = fmaf(w2, px[1], s);
        s = fmaf(w3, px[2], s);
        s = fmaf(w4, q0,    s);
        s = fmaf(w5, q1,    s);
        s = fmaf(w6, q2,    s);
    }
    float m = s;
#pragma unroll
    for (int off = 16; off; off >>= 1)
        m = fmaxf(m, __shfl_xor_sync(0xffffffffu, m, off));
    float e = (lane < KK) ? expf(s - m) : 0.0f;
    float sum = e;
#pragma unroll
    for (int off = 16; off; off >>= 1)
        sum += __shfl_xor_sync(0xffffffffu, sum, off);
    const float inv = 1.0f / sum;

    float4 acc = make_float4(0.f, 0.f, 0.f, 0.f);
    const float* nb = g_net + (size_t)b * TT * HH;
#pragma unroll
    for (int k = 0; k < KK; ++k) {
        float wk = __shfl_sync(0xffffffffu, e, k) * inv;
        int   jk = __shfl_sync(0xffffffffu, j, k);
        float4 v = *(const float4*)(nb + (size_t)jk * HH + lane * 4);
        acc.x = fmaf(wk, v.x, acc.x);
        acc.y = fmaf(wk, v.y, acc.y);
        acc.z = fmaf(wk, v.z, acc.z);
        acc.w = fmaf(wk, v.w, acc.w);
    }
    *(float4*)(g_att + (size_t)t * HH + lane * 4) = acc;
}

// ======================= fused resnet step ==============================
// a1 = att@Wo+bo ; x=[net,a1] ; h=relu(relu? no: relu(x)@W0+b0) ;
// out = x@Ws + (relu(h)@W1+b1) + (add_res? net : 0) ; g_net = out (in place)
#define XSTR 260
#define HSTR 132
#define FMA8(r, a)                                                    \
    acc[r][0] = fmaf(a, bv0.x, acc[r][0]);                            \
    acc[r][1] = fmaf(a, bv0.y, acc[r][1]);                            \
    acc[r][2] = fmaf(a, bv0.z, acc[r][2]);                            \
    acc[r][3] = fmaf(a, bv0.w, acc[r][3]);                            \
    acc[r][4] = fmaf(a, bv1.x, acc[r][4]);                            \
    acc[r][5] = fmaf(a, bv1.y, acc[r][5]);                            \
    acc[r][6] = fmaf(a, bv1.z, acc[r][6]);                            \
    acc[r][7] = fmaf(a, bv1.w, acc[r][7]);

#define LOAD_WTILE(WPTR, KTOT_UNUSED)                                               \
    __syncthreads();                                                                \
    for (int q = tid; q < 32 * 32; q += 256) {                                      \
        int kk = q >> 5, c = (q & 31) << 2;                                         \
        *(float4*)(ws + kk * 128 + c) =                                             \
            *(const float4*)((WPTR) + (size_t)(kt + kk) * 128 + c);                 \
    }                                                                               \
    __syncthreads();

__global__ __launch_bounds__(256) void resnet_kernel(
    const float* __restrict__ W0, const float* __restrict__ b0,
    const float* __restrict__ W1, const float* __restrict__ b1,
    const float* __restrict__ Wsc,
    const float* __restrict__ Wo, const float* __restrict__ bo,
    int add_res)
{
    extern __shared__ float sm[];
    float* xs = sm;                       // [64][XSTR]
    float* hs = sm + 64 * XSTR;           // [64][HSTR]
    float* ws = sm + 64 * XSTR + 64 * HSTR; // [32][128]

    const int tid = threadIdx.x;
    const int tx = tid & 15;        // output-dim group (8 dims)
    const int ty = tid >> 4;        // token group (4 tokens)
    const int nb = tx * 8;
    const int rb = ty * 4;
    const size_t t0 = (size_t)blockIdx.x * 64;

    // load net -> xs[:,0:128], att -> hs[:,0:128]
    for (int q = tid; q < 64 * 32; q += 256) {
        int r = q >> 5, c = (q & 31) << 2;
        *(float4*)(xs + r * XSTR + c) = *(const float4*)(g_net + (t0 + r) * HH + c);
        *(float4*)(hs + r * HSTR + c) = *(const float4*)(g_att + (t0 + r) * HH + c);
    }

    float acc[4][8];

    // ---- GEMM1: a1 = att @ Wo + bo -> xs[:,128:256]
#pragma unroll
    for (int r = 0; r < 4; ++r)
#pragma unroll
        for (int jj = 0; jj < 8; ++jj) acc[r][jj] = bo[nb + jj];
    for (int kt = 0; kt < 128; kt += 32) {
        LOAD_WTILE(Wo, 128)
#pragma unroll 8
        for (int kk = 0; kk < 32; ++kk) {
            float a0 = hs[(rb + 0) * HSTR + kt + kk];
            float a1 = hs[(rb + 1) * HSTR + kt + kk];
            float a2 = hs[(rb + 2) * HSTR + kt + kk];
            float a3 = hs[(rb + 3) * HSTR + kt + kk];
            float4 bv0 = *(const float4*)(ws + kk * 128 + nb);
            float4 bv1 = *(const float4*)(ws + kk * 128 + nb + 4);
            FMA8(0, a0) FMA8(1, a1) FMA8(2, a2) FMA8(3, a3)
        }
    }
    __syncthreads();
#pragma unroll
    for (int r = 0; r < 4; ++r) {
        *(float4*)(xs + (rb + r) * XSTR + 128 + nb)     = make_float4(acc[r][0], acc[r][1], acc[r][2], acc[r][3]);
        *(float4*)(xs + (rb + r) * XSTR + 128 + nb + 4) = make_float4(acc[r][4], acc[r][5], acc[r][6], acc[r][7]);
    }

    // ---- GEMM2: h = relu(x) @ W0 + b0 -> hs (stored relu'd)
#pragma unroll
    for (int r = 0; r < 4; ++r)
#pragma unroll
        for (int jj = 0; jj < 8; ++jj) acc[r][jj] = b0[nb + jj];
    for (int kt = 0; kt < 256; kt += 32) {
        LOAD_WTILE(W0, 256)
#pragma unroll 8
        for (int kk = 0; kk < 32; ++kk) {
            float a0 = fmaxf(xs[(rb + 0) * XSTR + kt + kk], 0.f);
            float a1 = fmaxf(xs[(rb + 1) * XSTR + kt + kk], 0.f);
            float a2 = fmaxf(xs[(rb + 2) * XSTR + kt + kk], 0.f);
            float a3 = fmaxf(xs[(rb + 3) * XSTR + kt + kk], 0.f);
            float4 bv0 = *(const float4*)(ws + kk * 128 + nb);
            float4 bv1 = *(const float4*)(ws + kk * 128 + nb + 4);
            FMA8(0, a0) FMA8(1, a1) FMA8(2, a2) FMA8(3, a3)
        }
    }
    __syncthreads();
#pragma unroll
    for (int r = 0; r < 4; ++r) {
        *(float4*)(hs + (rb + r) * HSTR + nb) =
            make_float4(fmaxf(acc[r][0], 0.f), fmaxf(acc[r][1], 0.f),
                        fmaxf(acc[r][2], 0.f), fmaxf(acc[r][3], 0.f));
        *(float4*)(hs + (rb + r) * HSTR + nb + 4) =
            make_float4(fmaxf(acc[r][4], 0.f), fmaxf(acc[r][5], 0.f),
                        fmaxf(acc[r][6], 0.f), fmaxf(acc[r][7], 0.f));
    }

    // ---- GEMM3+4: out = relu(h)@W1 + b1 + x@Ws [+ net]
#pragma unroll
    for (int r = 0; r < 4; ++r)
#pragma unroll
        for (int jj = 0; jj < 8; ++jj) acc[r][jj] = b1[nb + jj];
    for (int kt = 0; kt < 128; kt += 32) {
        LOAD_WTILE(W1, 128)
#pragma unroll 8
        for (int kk = 0; kk < 32; ++kk) {
            float a0 = hs[(rb + 0) * HSTR + kt + kk];
            float a1 = hs[(rb + 1) * HSTR + kt + kk];
            float a2 = hs[(rb + 2) * HSTR + kt + kk];
            float a3 = hs[(rb + 3) * HSTR + kt + kk];
            float4 bv0 = *(const float4*)(ws + kk * 128 + nb);
            float4 bv1 = *(const float4*)(ws + kk * 128 + nb + 4);
            FMA8(0, a0) FMA8(1, a1) FMA8(2, a2) FMA8(3, a3)
        }
    }
    for (int kt = 0; kt < 256; kt += 32) {
        LOAD_WTILE(Wsc, 256)
#pragma unroll 8
        for (int kk = 0; kk < 32; ++kk) {
            float a0 = xs[(rb + 0) * XSTR + kt + kk];
            float a1 = xs[(rb + 1) * XSTR + kt + kk];
            float a2 = xs[(rb + 2) * XSTR + kt + kk];
            float a3 = xs[(rb + 3) * XSTR + kt + kk];
            float4 bv0 = *(const float4*)(ws + kk * 128 + nb);
            float4 bv1 = *(const float4*)(ws + kk * 128 + nb + 4);
            FMA8(0, a0) FMA8(1, a1) FMA8(2, a2) FMA8(3, a3)
        }
    }
    if (add_res) {
#pragma unroll
        for (int r = 0; r < 4; ++r)
#pragma unroll
            for (int jj = 0; jj < 8; ++jj)
                acc[r][jj] += xs[(rb + r) * XSTR + nb + jj];
    }
#pragma unroll
    for (int r = 0; r < 4; ++r) {
        *(float4*)(g_net + (t0 + rb + r) * HH + nb)     = make_float4(acc[r][0], acc[r][1], acc[r][2], acc[r][3]);
        *(float4*)(g_net + (t0 + rb + r) * HH + nb + 4) = make_float4(acc[r][4], acc[r][5], acc[r][6], acc[r][7]);
    }
}

// ======================= final projection ===============================
__global__ __launch_bounds__(256) void final_kernel(const float* __restrict__ W_c,
                                                    const float* __restrict__ b_c,
                                                    float* __restrict__ out)
{
    extern __shared__ float sm[];
    float* xs = sm;             // [64][HSTR]
    float* ws = sm + 64 * HSTR; // [32][128]

    const int tid = threadIdx.x;
    const int tx = tid & 15;
    const int ty = tid >> 4;
    const int nb = tx * 8;
    const int rb = ty * 4;
    const size_t t0 = (size_t)blockIdx.x * 64;

    for (int q = tid; q < 64 * 32; q += 256) {
        int r = q >> 5, c = (q & 31) << 2;
        *(float4*)(xs + r * HSTR + c) = *(const float4*)(g_net + (t0 + r) * HH + c);
    }

    float acc[4][8];
#pragma unroll
    for (int r = 0; r < 4; ++r)
#pragma unroll
        for (int jj = 0; jj < 8; ++jj) acc[r][jj] = b_c[nb + jj];

    for (int kt = 0; kt < 128; kt += 32) {
        __syncthreads();
        for (int q = tid; q < 32 * 32; q += 256) {
            int kk = q >> 5, c = (q & 31) << 2;
            *(float4*)(ws + kk * 128 + c) = *(const float4*)(W_c + (size_t)(kt + kk) * 128 + c);
        }
        __syncthreads();
#pragma unroll 8
        for (int kk = 0; kk < 32; ++kk) {
            float a0 = xs[(rb + 0) * HSTR + kt + kk];
            float a1 = xs[(rb + 1) * HSTR + kt + kk];
            float a2 = xs[(rb + 2) * HSTR + kt + kk];
            float a3 = xs[(rb + 3) * HSTR + kt + kk];
            float4 bv0 = *(const float4*)(ws + kk * 128 + nb);
            float4 bv1 = *(const float4*)(ws + kk * 128 + nb + 4);
            FMA8(0, a0) FMA8(1, a1) FMA8(2, a2) FMA8(3, a3)
        }
    }
#pragma unroll
    for (int r = 0; r < 4; ++r) {
        *(float4*)(out + (t0 + rb + r) * HH + nb)     = make_float4(acc[r][0], acc[r][1], acc[r][2], acc[r][3]);
        *(float4*)(out + (t0 + rb + r) * HH + nb + 4) = make_float4(acc[r][4], acc[r][5], acc[r][6], acc[r][7]);
    }
}

// ======================= launch =========================================
extern "C" void kernel_launch(void* const* d_in, const int* in_sizes, int n_in,
                              void* d_out, int out_size)
{
    const float* p      = (const float*)d_in[0];
    const float* W_pos  = (const float*)d_in[1];
    const float* b_pos  = (const float*)d_in[2];
    const float* blk_W0 = (const float*)d_in[3];
    const float* blk_b0 = (const float*)d_in[4];
    const float* blk_W1 = (const float*)d_in[5];
    const float* blk_b1 = (const float*)d_in[6];
    const float* blk_Ws = (const float*)d_in[7];
    const float* att_Wc = (const float*)d_in[8];
    const float* att_bc = (const float*)d_in[9];
    const float* att_Wo = (const float*)d_in[10];
    const float* att_bo = (const float*)d_in[11];
    const float* W_c    = (const float*)d_in[12];
    const float* b_c    = (const float*)d_in[13];
    float* out = (float*)d_out;

    const int RES_SMEM = (64 * XSTR + 64 * HSTR + 32 * 128) * 4;   // 116,736 B
    const int FIN_SMEM = (64 * HSTR + 32 * 128) * 4;               // 50,176 B
    cudaFuncSetAttribute(resnet_kernel, cudaFuncAttributeMaxDynamicSharedMemorySize, RES_SMEM);
    cudaFuncSetAttribute(final_kernel,  cudaFuncAttributeMaxDynamicSharedMemorySize, FIN_SMEM);

    knn_kernel<<<dim3(TT / 128, BB), 128>>>(p);
    pos_kernel<<<(BT * HH) / 256, 256>>>(p, W_pos, b_pos);

    for (int i = 0; i < NBLK; ++i) {
        attn_kernel<<<BT / 8, 256>>>(p, att_Wc + (size_t)i * 7, att_bc + i);
        resnet_kernel<<<BT / 64, 256, RES_SMEM>>>(
            blk_W0 + (size_t)i * 256 * 128, blk_b0 + (size_t)i * 128,
            blk_W1 + (size_t)i * 128 * 128, blk_b1 + (size_t)i * 128,
            blk_Ws + (size_t)i * 256 * 128,
            att_Wo + (size_t)i * 128 * 128, att_bo + (size_t)i * 128,
            i > 0 ? 1 : 0);
    }
    final_kernel<<<BT / 64, 256, FIN_SMEM>>>(W_c, b_c, out);
}

// round 2
// speedup vs baseline: 1.4608x; 1.4608x over previous
#include <cuda_runtime.h>
#include <cuda_bf16.h>
#include <math.h>
#include <float.h>

#define BB 8
#define TT 4096
#define DD 3
#define HH 128
#define NBLK 6
#define KK 20
#define BT (BB*TT)   // 32768
#define SX 132       // smem row stride (floats) for 128-wide activation tiles

// ---------------- scratch (device globals; no allocation) ----------------
__device__ float g_net[BT * HH];   // 16 MB
__device__ float g_att[BT * HH];   // 16 MB
__device__ int   g_idx[BT * KK];
__device__ float g_dis[BT * KK];

// ======================= KNN ============================================
__global__ __launch_bounds__(128) void knn_kernel(const float* __restrict__ p)
{
    const int b  = blockIdx.y;
    const int tt = blockIdx.x * 128 + threadIdx.x;
    const float* pb = p + (size_t)b * TT * 3;

    const float qx = pb[tt*3 + 0];
    const float qy = pb[tt*3 + 1];
    const float qz = pb[tt*3 + 2];
    const float sqq = (qx*qx + qy*qy) + qz*qz;

    float bd[KK];
    int   bi[KK];
#pragma unroll
    for (int k = 0; k < KK; ++k) { bd[k] = FLT_MAX; bi[k] = 0; }

    __shared__ float4 sp[1024];   // x,y,z,|.|^2

    for (int s0 = 0; s0 < TT; s0 += 1024) {
        __syncthreads();
        for (int l = threadIdx.x; l < 1024; l += 128) {
            const float* q = pb + (size_t)(s0 + l) * 3;
            float x = q[0], y = q[1], z = q[2];
            sp[l] = make_float4(x, y, z, (x*x + y*y) + z*z);
        }
        __syncthreads();
#pragma unroll 4
        for (int l = 0; l < 1024; ++l) {
            float4 v = sp[l];
            float dot = qx*v.x + qy*v.y + qz*v.z;
            float d2  = sqq + v.w - 2.0f * dot;
            if (d2 < bd[KK-1]) {
                bd[KK-1] = d2; bi[KK-1] = s0 + l;
#pragma unroll
                for (int q2 = KK-1; q2 > 0; --q2) {
                    if (bd[q2] < bd[q2-1]) {
                        float td = bd[q2]; bd[q2] = bd[q2-1]; bd[q2-1] = td;
                        int   ti = bi[q2]; bi[q2] = bi[q2-1]; bi[q2-1] = ti;
                    }
                }
            }
        }
    }

    const size_t o = ((size_t)b * TT + tt) * KK;
#pragma unroll
    for (int k = 0; k < KK; ++k) {
        g_idx[o + k] = bi[k];
        g_dis[o + k] = sqrtf(fmaxf(bd[k], 1e-12f));
    }
}

// ======================= positional encoding ============================
__global__ __launch_bounds__(256) void pos_kernel(const float* __restrict__ p,
                                                  const float* __restrict__ W_pos,
                                                  const float* __restrict__ b_pos)
{
    int gid = blockIdx.x * 256 + threadIdx.x;   // < BT*HH
    int t = gid >> 7;
    int h = gid & 127;
    const float* pp = p + (size_t)t * 3;
    float v = b_pos[h];
    v = fmaf(pp[0], W_pos[h],        v);
    v = fmaf(pp[1], W_pos[HH + h],   v);
    v = fmaf(pp[2], W_pos[2*HH + h], v);
    g_net[gid] = v;
}

// ======================= attention (gather + softmax) ===================
__global__ __launch_bounds__(256) void attn_kernel(const float* __restrict__ p,
                                                   const float* __restrict__ wc,
                                                   const float* __restrict__ bc)
{
    const int warp = threadIdx.x >> 5;
    const int lane = threadIdx.x & 31;
    const int t  = blockIdx.x * 8 + warp;      // 0..BT-1
    const int b  = t >> 12;
    const int tt = t & (TT - 1);
    const float* pb = p + (size_t)b * TT * 3;

    const float q0 = pb[tt*3+0], q1 = pb[tt*3+1], q2 = pb[tt*3+2];
    const float w0 = wc[0], w1 = wc[1], w2 = wc[2], w3 = wc[3];
    const float w4 = wc[4], w5 = wc[5], w6 = wc[6], bcv = bc[0];

    float s = -FLT_MAX;
    int   j = 0;
    if (lane < KK) {
        size_t o = (size_t)t * KK + lane;
        j = g_idx[o];
        float d = g_dis[o];
        const float* px = pb + (size_t)j * 3;
        s = bcv;
        s = fmaf(w0, d,     s);
        s = fmaf(w1, px[0], s);
        s = fmaf(w2, px[1], s);
        s = fmaf(w3, px[2], s);
        s = fmaf(w4, q0,    s);
        s = fmaf(w5, q1,    s);
        s = fmaf(w6, q2,    s);
    }
    float m = s;
#pragma unroll
    for (int off = 16; off; off >>= 1)
        m = fmaxf(m, __shfl_xor_sync(0xffffffffu, m, off));
    float e = (lane < KK) ? expf(s - m) : 0.0f;
    float sum = e;
#pragma unroll
    for (int off = 16; off; off >>= 1)
        sum += __shfl_xor_sync(0xffffffffu, sum, off);
    const float inv = 1.0f / sum;

    float4 acc = make_float4(0.f, 0.f, 0.f, 0.f);
    const float* nb = g_net + (size_t)b * TT * HH;
#pragma unroll
    for (int k = 0; k < KK; ++k) {
        float wk = __shfl_sync(0xffffffffu, e, k) * inv;
        int   jk = __shfl_sync(0xffffffffu, j, k);
        float4 v = *(const float4*)(nb + (size_t)jk * HH + lane * 4);
        acc.x = fmaf(wk, v.x, acc.x);
        acc.y = fmaf(wk, v.y, acc.y);
        acc.z = fmaf(wk, v.z, acc.z);
        acc.w = fmaf(wk, v.w, acc.w);
    }
    *(float4*)(g_att + (size_t)t * HH + lane * 4) = acc;
}

// ======================= GEMM building block ============================
// 128-token x 128-dim tile, 256 threads, 8x8 register tile per thread.
// Ssm: smem activation source (row stride SX), Wg: gmem weights [128][128]
// (one 128-deep K chunk), acc accumulated in place.
template<bool RELU>
__device__ __forceinline__ void gemm_accum(
    const float* __restrict__ Wg,
    const float* Ssm, float* ws, float acc[8][8],
    int tid, int nb, int rb)
{
    for (int kt = 0; kt < 128; kt += 32) {
        __syncthreads();
#pragma unroll
        for (int q = tid; q < 1024; q += 256) {
            int kk = q >> 5, c = (q & 31) << 2;
            *(float4*)(ws + kk * 128 + c) =
                *(const float4*)(Wg + (size_t)(kt + kk) * 128 + c);
        }
        __syncthreads();
#pragma unroll 1
        for (int k4 = 0; k4 < 8; ++k4) {
            float4 a4[8];
#pragma unroll
            for (int r = 0; r < 8; ++r)
                a4[r] = *(const float4*)(Ssm + (rb + r) * SX + kt + k4 * 4);
#pragma unroll
            for (int j = 0; j < 4; ++j) {
                int kk = k4 * 4 + j;
                float4 bv0 = *(const float4*)(ws + kk * 128 + nb);
                float4 bv1 = *(const float4*)(ws + kk * 128 + nb + 4);
#pragma unroll
                for (int r = 0; r < 8; ++r) {
                    float a = ((const float*)&a4[r])[j];
                    if (RELU) a = fmaxf(a, 0.0f);
                    acc[r][0] = fmaf(a, bv0.x, acc[r][0]);
                    acc[r][1] = fmaf(a, bv0.y, acc[r][1]);
                    acc[r][2] = fmaf(a, bv0.z, acc[r][2]);
                    acc[r][3] = fmaf(a, bv0.w, acc[r][3]);
                    acc[r][4] = fmaf(a, bv1.x, acc[r][4]);
                    acc[r][5] = fmaf(a, bv1.y, acc[r][5]);
                    acc[r][6] = fmaf(a, bv1.z, acc[r][6]);
                    acc[r][7] = fmaf(a, bv1.w, acc[r][7]);
                }
            }
        }
    }
}

__device__ __forceinline__ void init_bias(float acc[8][8], const float* __restrict__ bias, int nb)
{
    float4 b0v = *(const float4*)(bias + nb);
    float4 b1v = *(const float4*)(bias + nb + 4);
#pragma unroll
    for (int r = 0; r < 8; ++r) {
        acc[r][0] = b0v.x; acc[r][1] = b0v.y; acc[r][2] = b0v.z; acc[r][3] = b0v.w;
        acc[r][4] = b1v.x; acc[r][5] = b1v.y; acc[r][6] = b1v.z; acc[r][7] = b1v.w;
    }
}

// ======================= fused resnet step ==============================
__global__ __launch_bounds__(256) void resnet_kernel(
    const float* __restrict__ W0, const float* __restrict__ b0,
    const float* __restrict__ W1, const float* __restrict__ b1,
    const float* __restrict__ Wsc,
    const float* __restrict__ Wo, const float* __restrict__ bo,
    int add_res)
{
    extern __shared__ float sm[];
    float* xs  = sm;                 // [128][SX] net
    float* as_ = sm + 128 * SX;      // [128][SX] a1 = att@Wo+bo
    float* hs  = sm + 2 * 128 * SX;  // [128][SX] att, then relu(h)
    float* ws  = sm + 3 * 128 * SX;  // [32][128]

    const int tid = threadIdx.x;
    const int tx = tid & 15;         // output-dim group (8 dims)
    const int ty = tid >> 4;         // token group (8 tokens)
    const int nb = tx * 8;
    const int rb = ty * 8;
    const size_t t0 = (size_t)blockIdx.x * 128;

    // load net -> xs, att -> hs
    for (int q = tid; q < 128 * 32; q += 256) {
        int r = q >> 5, c = (q & 31) << 2;
        *(float4*)(xs + r * SX + c) = *(const float4*)(g_net + (t0 + r) * HH + c);
        *(float4*)(hs + r * SX + c) = *(const float4*)(g_att + (t0 + r) * HH + c);
    }

    float acc[8][8];

    // ---- GEMM1: a1 = att @ Wo + bo  -> as_
    init_bias(acc, bo, nb);
    gemm_accum<false>(Wo, hs, ws, acc, tid, nb, rb);
#pragma unroll
    for (int r = 0; r < 8; ++r) {
        *(float4*)(as_ + (rb + r) * SX + nb)     = make_float4(acc[r][0], acc[r][1], acc[r][2], acc[r][3]);
        *(float4*)(as_ + (rb + r) * SX + nb + 4) = make_float4(acc[r][4], acc[r][5], acc[r][6], acc[r][7]);
    }

    // ---- GEMM2: h = relu([net|a1]) @ W0 + b0 -> hs (stored relu'd)
    init_bias(acc, b0, nb);
    gemm_accum<true>(W0,            xs,  ws, acc, tid, nb, rb);
    gemm_accum<true>(W0 + 128*128,  as_, ws, acc, tid, nb, rb);
    __syncthreads();   // everyone done reading hs (att) before overwrite
#pragma unroll
    for (int r = 0; r < 8; ++r) {
        *(float4*)(hs + (rb + r) * SX + nb) =
            make_float4(fmaxf(acc[r][0], 0.f), fmaxf(acc[r][1], 0.f),
                        fmaxf(acc[r][2], 0.f), fmaxf(acc[r][3], 0.f));
        *(float4*)(hs + (rb + r) * SX + nb + 4) =
            make_float4(fmaxf(acc[r][4], 0.f), fmaxf(acc[r][5], 0.f),
                        fmaxf(acc[r][6], 0.f), fmaxf(acc[r][7], 0.f));
    }

    // ---- GEMM3+4: out = relu(h)@W1 + b1 + [net|a1]@Ws [+ net residual]
    init_bias(acc, b1, nb);
    gemm_accum<false>(W1,            hs,  ws, acc, tid, nb, rb);
    gemm_accum<false>(Wsc,           xs,  ws, acc, tid, nb, rb);
    gemm_accum<false>(Wsc + 128*128, as_, ws, acc, tid, nb, rb);

    if (add_res) {
#pragma unroll
        for (int r = 0; r < 8; ++r) {
            float4 x0 = *(const float4*)(xs + (rb + r) * SX + nb);
            float4 x1 = *(const float4*)(xs + (rb + r) * SX + nb + 4);
            acc[r][0] += x0.x; acc[r][1] += x0.y; acc[r][2] += x0.z; acc[r][3] += x0.w;
            acc[r][4] += x1.x; acc[r][5] += x1.y; acc[r][6] += x1.z; acc[r][7] += x1.w;
        }
    }
#pragma unroll
    for (int r = 0; r < 8; ++r) {
        *(float4*)(g_net + (t0 + rb + r) * HH + nb)     = make_float4(acc[r][0], acc[r][1], acc[r][2], acc[r][3]);
        *(float4*)(g_net + (t0 + rb + r) * HH + nb + 4) = make_float4(acc[r][4], acc[r][5], acc[r][6], acc[r][7]);
    }
}

// ======================= final projection ===============================
__global__ __launch_bounds__(256) void final_kernel(const float* __restrict__ W_c,
                                                    const float* __restrict__ b_c,
                                                    float* __restrict__ out)
{
    extern __shared__ float sm[];
    float* xs = sm;              // [128][SX]
    float* ws = sm + 128 * SX;   // [32][128]

    const int tid = threadIdx.x;
    const int tx = tid & 15;
    const int ty = tid >> 4;
    const int nb = tx * 8;
    const int rb = ty * 8;
    const size_t t0 = (size_t)blockIdx.x * 128;

    for (int q = tid; q < 128 * 32; q += 256) {
        int r = q >> 5, c = (q & 31) << 2;
        *(float4*)(xs + r * SX + c) = *(const float4*)(g_net + (t0 + r) * HH + c);
    }

    float acc[8][8];
    init_bias(acc, b_c, nb);
    gemm_accum<false>(W_c, xs, ws, acc, tid, nb, rb);

#pragma unroll
    for (int r = 0; r < 8; ++r) {
        *(float4*)(out + (t0 + rb + r) * HH + nb)     = make_float4(acc[r][0], acc[r][1], acc[r][2], acc[r][3]);
        *(float4*)(out + (t0 + rb + r) * HH + nb + 4) = make_float4(acc[r][4], acc[r][5], acc[r][6], acc[r][7]);
    }
}

// ======================= launch =========================================
extern "C" void kernel_launch(void* const* d_in, const int* in_sizes, int n_in,
                              void* d_out, int out_size)
{
    const float* p      = (const float*)d_in[0];
    const float* W_pos  = (const float*)d_in[1];
    const float* b_pos  = (const float*)d_in[2];
    const float* blk_W0 = (const float*)d_in[3];
    const float* blk_b0 = (const float*)d_in[4];
    const float* blk_W1 = (const float*)d_in[5];
    const float* blk_b1 = (const float*)d_in[6];
    const float* blk_Ws = (const float*)d_in[7];
    const float* att_Wc = (const float*)d_in[8];
    const float* att_bc = (const float*)d_in[9];
    const float* att_Wo = (const float*)d_in[10];
    const float* att_bo = (const float*)d_in[11];
    const float* W_c    = (const float*)d_in[12];
    const float* b_c    = (const float*)d_in[13];
    float* out = (float*)d_out;

    const int RES_SMEM = (3 * 128 * SX + 32 * 128) * 4;   // 219,136 B
    const int FIN_SMEM = (128 * SX + 32 * 128) * 4;       //  83,968 B
    static int configured = 0;
    cudaFuncSetAttribute(resnet_kernel, cudaFuncAttributeMaxDynamicSharedMemorySize, RES_SMEM);
    cudaFuncSetAttribute(final_kernel,  cudaFuncAttributeMaxDynamicSharedMemorySize, FIN_SMEM);
    (void)configured;

    knn_kernel<<<dim3(TT / 128, BB), 128>>>(p);
    pos_kernel<<<(BT * HH) / 256, 256>>>(p, W_pos, b_pos);

    for (int i = 0; i < NBLK; ++i) {
        attn_kernel<<<BT / 8, 256>>>(p, att_Wc + (size_t)i * 7, att_bc + i);
        resnet_kernel<<<BT / 128, 256, RES_SMEM>>>(
            blk_W0 + (size_t)i * 256 * 128, blk_b0 + (size_t)i * 128,
            blk_W1 + (size_t)i * 128 * 128, blk_b1 + (size_t)i * 128,
            blk_Ws + (size_t)i * 256 * 128,
            att_Wo + (size_t)i * 128 * 128, att_bo + (size_t)i * 128,
            i > 0 ? 1 : 0);
    }
    final_kernel<<<BT / 128, 256, FIN_SMEM>>>(W_c, b_c, out);
}

// round 3
// speedup vs baseline: 1.4874x; 1.0182x over previous
#include <cuda_runtime.h>
#include <cuda_bf16.h>
#include <math.h>
#include <float.h>

#define BB 8
#define TT 4096
#define DD 3
#define HH 128
#define NBLK 6
#define KK 20
#define BT (BB*TT)   // 32768
#define SX 132       // smem row stride (floats) for 128-wide activation tiles

typedef unsigned long long u64;

// packed f32x2 helpers (sm_103a)
#define FMA2(d, a, b, c) \
    asm("fma.rn.f32x2 %0, %1, %2, %3;" : "=l"(d) : "l"(a), "l"(b), "l"(c))
#define ADD2(d, a, b) \
    asm("add.rn.f32x2 %0, %1, %2;" : "=l"(d) : "l"(a), "l"(b))
#define BCAST2(d, s) \
    asm("mov.b64 %0, {%1, %1};" : "=l"(d) : "r"(s))
#define UNPK2(lo, hi, s) \
    asm("mov.b64 {%0, %1}, %2;" : "=r"(lo), "=r"(hi) : "l"(s))

// ---------------- scratch (device globals; no allocation) ----------------
__device__ float g_net[BT * HH];   // 16 MB
__device__ float g_att[BT * HH];   // 16 MB
__device__ int   g_idx[BT * KK];
__device__ float g_dis[BT * KK];

// ======================= KNN ============================================
__global__ __launch_bounds__(128) void knn_kernel(const float* __restrict__ p)
{
    const int b  = blockIdx.y;
    const int tt = blockIdx.x * 128 + threadIdx.x;
    const float* pb = p + (size_t)b * TT * 3;

    const float qx = pb[tt*3 + 0];
    const float qy = pb[tt*3 + 1];
    const float qz = pb[tt*3 + 2];
    const float sqq = (qx*qx + qy*qy) + qz*qz;

    float bd[KK];
    int   bi[KK];
#pragma unroll
    for (int k = 0; k < KK; ++k) { bd[k] = FLT_MAX; bi[k] = 0; }

    __shared__ float4 sp[1024];   // x,y,z,|.|^2

    for (int s0 = 0; s0 < TT; s0 += 1024) {
        __syncthreads();
        for (int l = threadIdx.x; l < 1024; l += 128) {
            const float* q = pb + (size_t)(s0 + l) * 3;
            float x = q[0], y = q[1], z = q[2];
            sp[l] = make_float4(x, y, z, (x*x + y*y) + z*z);
        }
        __syncthreads();
#pragma unroll 4
        for (int l = 0; l < 1024; ++l) {
            float4 v = sp[l];
            float dot = qx*v.x + qy*v.y + qz*v.z;
            float d2  = sqq + v.w - 2.0f * dot;
            if (d2 < bd[KK-1]) {
                bd[KK-1] = d2; bi[KK-1] = s0 + l;
#pragma unroll
                for (int q2 = KK-1; q2 > 0; --q2) {
                    if (bd[q2] < bd[q2-1]) {
                        float td = bd[q2]; bd[q2] = bd[q2-1]; bd[q2-1] = td;
                        int   ti = bi[q2]; bi[q2] = bi[q2-1]; bi[q2-1] = ti;
                    }
                }
            }
        }
    }

    const size_t o = ((size_t)b * TT + tt) * KK;
#pragma unroll
    for (int k = 0; k < KK; ++k) {
        g_idx[o + k] = bi[k];
        g_dis[o + k] = sqrtf(fmaxf(bd[k], 1e-12f));
    }
}

// ======================= positional encoding ============================
__global__ __launch_bounds__(256) void pos_kernel(const float* __restrict__ p,
                                                  const float* __restrict__ W_pos,
                                                  const float* __restrict__ b_pos)
{
    int gid = blockIdx.x * 256 + threadIdx.x;   // < BT*HH
    int t = gid >> 7;
    int h = gid & 127;
    const float* pp = p + (size_t)t * 3;
    float v = b_pos[h];
    v = fmaf(pp[0], W_pos[h],        v);
    v = fmaf(pp[1], W_pos[HH + h],   v);
    v = fmaf(pp[2], W_pos[2*HH + h], v);
    g_net[gid] = v;
}

// ======================= attention (gather + softmax) ===================
__global__ __launch_bounds__(256) void attn_kernel(const float* __restrict__ p,
                                                   const float* __restrict__ wc,
                                                   const float* __restrict__ bc)
{
    const int warp = threadIdx.x >> 5;
    const int lane = threadIdx.x & 31;
    const int t  = blockIdx.x * 8 + warp;      // 0..BT-1
    const int b  = t >> 12;
    const int tt = t & (TT - 1);
    const float* pb = p + (size_t)b * TT * 3;

    const float q0 = pb[tt*3+0], q1 = pb[tt*3+1], q2 = pb[tt*3+2];
    const float w0 = wc[0], w1 = wc[1], w2 = wc[2], w3 = wc[3];
    const float w4 = wc[4], w5 = wc[5], w6 = wc[6], bcv = bc[0];

    float s = -FLT_MAX;
    int   j = 0;
    if (lane < KK) {
        size_t o = (size_t)t * KK + lane;
        j = g_idx[o];
        float d = g_dis[o];
        const float* px = pb + (size_t)j * 3;
        s = bcv;
        s = fmaf(w0, d,     s);
        s = fmaf(w1, px[0], s);
        s = fmaf(w2, px[1], s);
        s = fmaf(w3, px[2], s);
        s = fmaf(w4, q0,    s);
        s = fmaf(w5, q1,    s);
        s = fmaf(w6, q2,    s);
    }
    float m = s;
#pragma unroll
    for (int off = 16; off; off >>= 1)
        m = fmaxf(m, __shfl_xor_sync(0xffffffffu, m, off));
    float e = (lane < KK) ? expf(s - m) : 0.0f;
    float sum = e;
#pragma unroll
    for (int off = 16; off; off >>= 1)
        sum += __shfl_xor_sync(0xffffffffu, sum, off);
    const float inv = 1.0f / sum;

    float4 acc = make_float4(0.f, 0.f, 0.f, 0.f);
    const float* nb = g_net + (size_t)b * TT * HH;
#pragma unroll
    for (int k = 0; k < KK; ++k) {
        float wk = __shfl_sync(0xffffffffu, e, k) * inv;
        int   jk = __shfl_sync(0xffffffffu, j, k);
        float4 v = *(const float4*)(nb + (size_t)jk * HH + lane * 4);
        acc.x = fmaf(wk, v.x, acc.x);
        acc.y = fmaf(wk, v.y, acc.y);
        acc.z = fmaf(wk, v.z, acc.z);
        acc.w = fmaf(wk, v.w, acc.w);
    }
    *(float4*)(g_att + (size_t)t * HH + lane * 4) = acc;
}

// ======================= GEMM building block ============================
// 128-token x 128-dim tile, 256 threads, 8x8 register tile per thread,
// accumulators held as packed f32x2 (FFMA2). One 128-deep K chunk.
// Next-weight-tile prefetch into registers hides LDG latency.
template<bool RELU>
__device__ __forceinline__ void gemm_accum(
    const float* __restrict__ Wg,
    const float* Ssm, float* ws, u64 acc[8][4],
    int tid, int nb, int rb)
{
    const int prow = tid >> 5;          // base row for this thread's 4 copy slots
    const int pcol = (tid & 31) << 2;

    float4 pre[4];
#pragma unroll
    for (int i = 0; i < 4; ++i)
        pre[i] = *(const float4*)(Wg + (size_t)(prow + i * 8) * 128 + pcol);

    for (int kt = 0; kt < 128; kt += 32) {
        __syncthreads();
#pragma unroll
        for (int i = 0; i < 4; ++i)
            *(float4*)(ws + (prow + i * 8) * 128 + pcol) = pre[i];
        __syncthreads();
        if (kt < 96) {
            const float* Wn = Wg + (size_t)(kt + 32) * 128;
#pragma unroll
            for (int i = 0; i < 4; ++i)
                pre[i] = *(const float4*)(Wn + (size_t)(prow + i * 8) * 128 + pcol);
        }
#pragma unroll 1
        for (int k4 = 0; k4 < 8; ++k4) {
            float4 a4[8];
#pragma unroll
            for (int r = 0; r < 8; ++r)
                a4[r] = *(const float4*)(Ssm + (rb + r) * SX + kt + k4 * 4);
#pragma unroll
            for (int j = 0; j < 4; ++j) {
                int kk = k4 * 4 + j;
                ulonglong2 b0 = *(const ulonglong2*)(ws + kk * 128 + nb);
                ulonglong2 b1 = *(const ulonglong2*)(ws + kk * 128 + nb + 4);
#pragma unroll
                for (int r = 0; r < 8; ++r) {
                    float a = ((const float*)&a4[r])[j];
                    if (RELU) a = fmaxf(a, 0.0f);
                    u64 aa; BCAST2(aa, __float_as_uint(a));
                    FMA2(acc[r][0], aa, b0.x, acc[r][0]);
                    FMA2(acc[r][1], aa, b0.y, acc[r][1]);
                    FMA2(acc[r][2], aa, b1.x, acc[r][2]);
                    FMA2(acc[r][3], aa, b1.y, acc[r][3]);
                }
            }
        }
    }
}

__device__ __forceinline__ void init_bias(u64 acc[8][4], const float* __restrict__ bias, int nb)
{
    ulonglong2 q0 = *(const ulonglong2*)(bias + nb);
    ulonglong2 q1 = *(const ulonglong2*)(bias + nb + 4);
#pragma unroll
    for (int r = 0; r < 8; ++r) {
        acc[r][0] = q0.x; acc[r][1] = q0.y; acc[r][2] = q1.x; acc[r][3] = q1.y;
    }
}

// ======================= fused resnet step ==============================
__global__ __launch_bounds__(256) void resnet_kernel(
    const float* __restrict__ W0, const float* __restrict__ b0,
    const float* __restrict__ W1, const float* __restrict__ b1,
    const float* __restrict__ Wsc,
    const float* __restrict__ Wo, const float* __restrict__ bo,
    int add_res)
{
    extern __shared__ float sm[];
    float* xs  = sm;                 // [128][SX] net
    float* as_ = sm + 128 * SX;      // [128][SX] a1 = att@Wo+bo
    float* hs  = sm + 2 * 128 * SX;  // [128][SX] att, then relu(h)
    float* ws  = sm + 3 * 128 * SX;  // [32][128]

    const int tid = threadIdx.x;
    const int tx = tid & 15;         // output-dim group (8 dims)
    const int ty = tid >> 4;         // token group (8 tokens)
    const int nb = tx * 8;
    const int rb = ty * 8;
    const size_t t0 = (size_t)blockIdx.x * 128;

    // load net -> xs, att -> hs
    for (int q = tid; q < 128 * 32; q += 256) {
        int r = q >> 5, c = (q & 31) << 2;
        *(float4*)(xs + r * SX + c) = *(const float4*)(g_net + (t0 + r) * HH + c);
        *(float4*)(hs + r * SX + c) = *(const float4*)(g_att + (t0 + r) * HH + c);
    }

    u64 acc[8][4];

    // ---- GEMM1: a1 = att @ Wo + bo  -> as_
    init_bias(acc, bo, nb);
    gemm_accum<false>(Wo, hs, ws, acc, tid, nb, rb);
#pragma unroll
    for (int r = 0; r < 8; ++r) {
        *(ulonglong2*)(as_ + (rb + r) * SX + nb)     = make_ulonglong2(acc[r][0], acc[r][1]);
        *(ulonglong2*)(as_ + (rb + r) * SX + nb + 4) = make_ulonglong2(acc[r][2], acc[r][3]);
    }

    // ---- GEMM2: h = relu([net|a1]) @ W0 + b0 -> hs (stored relu'd)
    init_bias(acc, b0, nb);
    gemm_accum<true>(W0,            xs,  ws, acc, tid, nb, rb);
    gemm_accum<true>(W0 + 128*128,  as_, ws, acc, tid, nb, rb);
    __syncthreads();   // everyone done reading hs (att) before overwrite
#pragma unroll
    for (int r = 0; r < 8; ++r) {
#pragma unroll
        for (int c = 0; c < 4; ++c) {
            unsigned lo, hi; UNPK2(lo, hi, acc[r][c]);
            float flo = fmaxf(__uint_as_float(lo), 0.0f);
            float fhi = fmaxf(__uint_as_float(hi), 0.0f);
            *(float2*)(hs + (rb + r) * SX + nb + c * 2) = make_float2(flo, fhi);
        }
    }

    // ---- GEMM3+4: out = relu(h)@W1 + b1 + [net|a1]@Ws [+ net residual]
    init_bias(acc, b1, nb);
    gemm_accum<false>(W1,            hs,  ws, acc, tid, nb, rb);
    gemm_accum<false>(Wsc,           xs,  ws, acc, tid, nb, rb);
    gemm_accum<false>(Wsc + 128*128, as_, ws, acc, tid, nb, rb);

    if (add_res) {
#pragma unroll
        for (int r = 0; r < 8; ++r) {
            ulonglong2 x0 = *(const ulonglong2*)(xs + (rb + r) * SX + nb);
            ulonglong2 x1 = *(const ulonglong2*)(xs + (rb + r) * SX + nb + 4);
            ADD2(acc[r][0], acc[r][0], x0.x);
            ADD2(acc[r][1], acc[r][1], x0.y);
            ADD2(acc[r][2], acc[r][2], x1.x);
            ADD2(acc[r][3], acc[r][3], x1.y);
        }
    }
#pragma unroll
    for (int r = 0; r < 8; ++r) {
        *(ulonglong2*)(g_net + (t0 + rb + r) * HH + nb)     = make_ulonglong2(acc[r][0], acc[r][1]);
        *(ulonglong2*)(g_net + (t0 + rb + r) * HH + nb + 4) = make_ulonglong2(acc[r][2], acc[r][3]);
    }
}

// ======================= final projection ===============================
__global__ __launch_bounds__(256) void final_kernel(const float* __restrict__ W_c,
                                                    const float* __restrict__ b_c,
                                                    float* __restrict__ out)
{
    extern __shared__ float sm[];
    float* xs = sm;              // [128][SX]
    float* ws = sm + 128 * SX;   // [32][128]

    const int tid = threadIdx.x;
    const int tx = tid & 15;
    const int ty = tid >> 4;
    const int nb = tx * 8;
    const int rb = ty * 8;
    const size_t t0 = (size_t)blockIdx.x * 128;

    for (int q = tid; q < 128 * 32; q += 256) {
        int r = q >> 5, c = (q & 31) << 2;
        *(float4*)(xs + r * SX + c) = *(const float4*)(g_net + (t0 + r) * HH + c);
    }

    u64 acc[8][4];
    init_bias(acc, b_c, nb);
    gemm_accum<false>(W_c, xs, ws, acc, tid, nb, rb);

#pragma unroll
    for (int r = 0; r < 8; ++r) {
        *(ulonglong2*)(out + (t0 + rb + r) * HH + nb)     = make_ulonglong2(acc[r][0], acc[r][1]);
        *(ulonglong2*)(out + (t0 + rb + r) * HH + nb + 4) = make_ulonglong2(acc[r][2], acc[r][3]);
    }
}

// ======================= launch =========================================
extern "C" void kernel_launch(void* const* d_in, const int* in_sizes, int n_in,
                              void* d_out, int out_size)
{
    const float* p      = (const float*)d_in[0];
    const float* W_pos  = (const float*)d_in[1];
    const float* b_pos  = (const float*)d_in[2];
    const float* blk_W0 = (const float*)d_in[3];
    const float* blk_b0 = (const float*)d_in[4];
    const float* blk_W1 = (const float*)d_in[5];
    const float* blk_b1 = (const float*)d_in[6];
    const float* blk_Ws = (const float*)d_in[7];
    const float* att_Wc = (const float*)d_in[8];
    const float* att_bc = (const float*)d_in[9];
    const float* att_Wo = (const float*)d_in[10];
    const float* att_bo = (const float*)d_in[11];
    const float* W_c    = (const float*)d_in[12];
    const float* b_c    = (const float*)d_in[13];
    float* out = (float*)d_out;

    const int RES_SMEM = (3 * 128 * SX + 32 * 128) * 4;   // 219,136 B
    const int FIN_SMEM = (128 * SX + 32 * 128) * 4;       //  83,968 B
    cudaFuncSetAttribute(resnet_kernel, cudaFuncAttributeMaxDynamicSharedMemorySize, RES_SMEM);
    cudaFuncSetAttribute(final_kernel,  cudaFuncAttributeMaxDynamicSharedMemorySize, FIN_SMEM);

    knn_kernel<<<dim3(TT / 128, BB), 128>>>(p);
    pos_kernel<<<(BT * HH) / 256, 256>>>(p, W_pos, b_pos);

    for (int i = 0; i < NBLK; ++i) {
        attn_kernel<<<BT / 8, 256>>>(p, att_Wc + (size_t)i * 7, att_bc + i);
        resnet_kernel<<<BT / 128, 256, RES_SMEM>>>(
            blk_W0 + (size_t)i * 256 * 128, blk_b0 + (size_t)i * 128,
            blk_W1 + (size_t)i * 128 * 128, blk_b1 + (size_t)i * 128,
            blk_Ws + (size_t)i * 256 * 128,
            att_Wo + (size_t)i * 128 * 128, att_bo + (size_t)i * 128,
            i > 0 ? 1 : 0);
    }
    final_kernel<<<BT / 128, 256, FIN_SMEM>>>(W_c, b_c, out);
}

// round 5
// speedup vs baseline: 1.7517x; 1.1777x over previous
#include <cuda_runtime.h>
#include <cuda_bf16.h>
#include <math.h>
#include <float.h>
#include <stdint.h>

#define BB 8
#define TT 4096
#define HH 128
#define NBLK 6
#define KK 20
#define BT (BB*TT)   // 32768
#define SX 132       // activation tile stride (floats)
#define BSTR 136     // B chunk stride (floats)

typedef unsigned long long u64;

// packed f32x2 helpers (scalar kernels)
#define FMA2(d, a, b, c) \
    asm("fma.rn.f32x2 %0, %1, %2, %3;" : "=l"(d) : "l"(a), "l"(b), "l"(c))
#define BCAST2(d, s) \
    asm("mov.b64 %0, {%1, %1};" : "=l"(d) : "r"(s))

// tf32 mma (sm_80+ PTX, valid at target sm_103)
#define MMA_TF32(d, a, b) \
    asm volatile("mma.sync.aligned.m16n8k8.row.col.f32.tf32.tf32.f32 " \
        "{%0,%1,%2,%3}, {%4,%5,%6,%7}, {%8,%9}, {%0,%1,%2,%3};" \
        : "+f"((d)[0]), "+f"((d)[1]), "+f"((d)[2]), "+f"((d)[3]) \
        : "r"((a)[0]), "r"((a)[1]), "r"((a)[2]), "r"((a)[3]), \
          "r"((b)[0]), "r"((b)[1]))

__device__ __forceinline__ uint32_t tf32_hi(float v) {
    uint32_t h; asm("cvt.rna.tf32.f32 %0, %1;" : "=r"(h) : "f"(v));
    return h;
}

// ---------------- scratch (device globals; no allocation) ----------------
__device__ float g_net[BT * HH];   // 16 MB
__device__ float g_att[BT * HH];   // 16 MB
__device__ int   g_idx[BT * KK];
__device__ float g_dis[BT * KK];
// prepped weights: per block 48 K16-chunks x (hi 2048 + lo 2048 floats)
__device__ float g_bprep[NBLK * 48 * 4096];   // 4.7 MB

// ======================= KNN ============================================
__global__ __launch_bounds__(128) void knn_kernel(const float* __restrict__ p)
{
    const int b  = blockIdx.y;
    const int tt = blockIdx.x * 128 + threadIdx.x;
    const float* pb = p + (size_t)b * TT * 3;

    const float qx = pb[tt*3 + 0];
    const float qy = pb[tt*3 + 1];
    const float qz = pb[tt*3 + 2];
    const float sqq = (qx*qx + qy*qy) + qz*qz;

    float bd[KK];
    int   bi[KK];
#pragma unroll
    for (int k = 0; k < KK; ++k) { bd[k] = FLT_MAX; bi[k] = 0; }

    __shared__ float4 sp[1024];

    for (int s0 = 0; s0 < TT; s0 += 1024) {
        __syncthreads();
        for (int l = threadIdx.x; l < 1024; l += 128) {
            const float* q = pb + (size_t)(s0 + l) * 3;
            float x = q[0], y = q[1], z = q[2];
            sp[l] = make_float4(x, y, z, (x*x + y*y) + z*z);
        }
        __syncthreads();
#pragma unroll 4
        for (int l = 0; l < 1024; ++l) {
            float4 v = sp[l];
            float dot = qx*v.x + qy*v.y + qz*v.z;
            float d2  = sqq + v.w - 2.0f * dot;
            if (d2 < bd[KK-1]) {
                bd[KK-1] = d2; bi[KK-1] = s0 + l;
#pragma unroll
                for (int q2 = KK-1; q2 > 0; --q2) {
                    if (bd[q2] < bd[q2-1]) {
                        float td = bd[q2]; bd[q2] = bd[q2-1]; bd[q2-1] = td;
                        int   ti = bi[q2]; bi[q2] = bi[q2-1]; bi[q2-1] = ti;
                    }
                }
            }
        }
    }

    const size_t o = ((size_t)b * TT + tt) * KK;
#pragma unroll
    for (int k = 0; k < KK; ++k) {
        g_idx[o + k] = bi[k];
        g_dis[o + k] = sqrtf(fmaxf(bd[k], 1e-12f));
    }
}

// ======================= positional encoding ============================
__global__ __launch_bounds__(256) void pos_kernel(const float* __restrict__ p,
                                                  const float* __restrict__ W_pos,
                                                  const float* __restrict__ b_pos)
{
    int gid = blockIdx.x * 256 + threadIdx.x;
    int t = gid >> 7;
    int h = gid & 127;
    const float* pp = p + (size_t)t * 3;
    float v = b_pos[h];
    v = fmaf(pp[0], W_pos[h],        v);
    v = fmaf(pp[1], W_pos[HH + h],   v);
    v = fmaf(pp[2], W_pos[2*HH + h], v);
    g_net[gid] = v;
}

// ======================= attention (gather + softmax) ===================
__global__ __launch_bounds__(256) void attn_kernel(const float* __restrict__ p,
                                                   const float* __restrict__ wc,
                                                   const float* __restrict__ bc)
{
    const int warp = threadIdx.x >> 5;
    const int lane = threadIdx.x & 31;
    const int t  = blockIdx.x * 8 + warp;
    const int b  = t >> 12;
    const int tt = t & (TT - 1);
    const float* pb = p + (size_t)b * TT * 3;

    const float q0 = pb[tt*3+0], q1 = pb[tt*3+1], q2 = pb[tt*3+2];
    const float w0 = wc[0], w1 = wc[1], w2 = wc[2], w3 = wc[3];
    const float w4 = wc[4], w5 = wc[5], w6 = wc[6], bcv = bc[0];

    float s = -FLT_MAX;
    int   j = 0;
    if (lane < KK) {
        size_t o = (size_t)t * KK + lane;
        j = g_idx[o];
        float d = g_dis[o];
        const float* px = pb + (size_t)j * 3;
        s = bcv;
        s = fmaf(w0, d,     s);
        s = fmaf(w1, px[0], s);
        s = fmaf(w2, px[1], s);
        s = fmaf(w3, px[2], s);
        s = fmaf(w4, q0,    s);
        s = fmaf(w5, q1,    s);
        s = fmaf(w6, q2,    s);
    }
    float m = s;
#pragma unroll
    for (int off = 16; off; off >>= 1)
        m = fmaxf(m, __shfl_xor_sync(0xffffffffu, m, off));
    float e = (lane < KK) ? expf(s - m) : 0.0f;
    float sum = e;
#pragma unroll
    for (int off = 16; off; off >>= 1)
        sum += __shfl_xor_sync(0xffffffffu, sum, off);
    const float inv = 1.0f / sum;

    float4 acc = make_float4(0.f, 0.f, 0.f, 0.f);
    const float* nb = g_net + (size_t)b * TT * HH;
#pragma unroll
    for (int k = 0; k < KK; ++k) {
        float wk = __shfl_sync(0xffffffffu, e, k) * inv;
        int   jk = __shfl_sync(0xffffffffu, j, k);
        float4 v = *(const float4*)(nb + (size_t)jk * HH + lane * 4);
        acc.x = fmaf(wk, v.x, acc.x);
        acc.y = fmaf(wk, v.y, acc.y);
        acc.z = fmaf(wk, v.z, acc.z);
        acc.w = fmaf(wk, v.w, acc.w);
    }
    *(float4*)(g_att + (size_t)t * HH + lane * 4) = acc;
}

// ======================= weight prep ====================================
// 48 K16-chunk slots per block:
//   Wo: 0..7, W0: 8..23 (K=256), W1: 24..31, Ws: 32..47 (K=256)
// Each chunk image: hi[16*128] then lo[16*128], layout B[kk][n] = W[k][n],
// tf32 hi/lo split, stored linear (kk*128+n).
__global__ __launch_bounds__(256) void prep_weights(
    const float* __restrict__ Wo, const float* __restrict__ W0,
    const float* __restrict__ W1, const float* __restrict__ Ws)
{
    const int blk = blockIdx.y;
    const int slot = blockIdx.x;
    const float* W; int ck;
    if (slot < 8)       { W = Wo + (size_t)blk*128*128; ck = slot; }
    else if (slot < 24) { W = W0 + (size_t)blk*256*128; ck = slot-8; }
    else if (slot < 32) { W = W1 + (size_t)blk*128*128; ck = slot-24; }
    else                { W = Ws + (size_t)blk*256*128; ck = slot-32; }
    float* img = g_bprep + ((size_t)blk*48 + slot)*4096;

    for (int idx = threadIdx.x; idx < 2048; idx += 256) {
        int kk = idx >> 7, n = idx & 127;
        float v = W[(size_t)(ck*16 + kk)*128 + n];
        uint32_t h = tf32_hi(v);
        float hv = __uint_as_float(h);
        uint32_t l = tf32_hi(v - hv);
        img[idx]        = hv;
        img[2048 + idx] = __uint_as_float(l);
    }
}

// ======================= tensor-core resnet =============================
// 256 threads, 8 warps; warp tile 32 rows x 64 cols.
// acc[mt][j][c]: mt = m16-tile (rows rb+mt*16..), j = n8-tile, c = frag elem.

__device__ __forceinline__ void init_acc(float acc[2][8][4],
                                         const float* __restrict__ bias,
                                         int nb, int tig)
{
#pragma unroll
    for (int j = 0; j < 8; ++j) {
        int col0 = nb + j*8 + 2*tig;
        float b0v = __ldg(bias + col0);
        float b1v = __ldg(bias + col0 + 1);
#pragma unroll
        for (int mt = 0; mt < 2; ++mt) {
            acc[mt][j][0] = b0v; acc[mt][j][1] = b1v;
            acc[mt][j][2] = b0v; acc[mt][j][3] = b1v;
        }
    }
}

template<bool RELU>
__device__ __forceinline__ void gemm_tc(
    const float* As, const float* __restrict__ prep, int nchunks,
    float acc[2][8][4], float* Bs, int tid, int rb, int nb)
{
    const int lane = tid & 31;
    const int gid = lane >> 2, tig = lane & 3;

    for (int c = 0; c < nchunks; ++c) {
        __syncthreads();
        // stage B chunk: hi -> Bs[0..], lo -> Bs[16*BSTR..] (padded stride)
        const float* src = prep + (size_t)c * 4096;
#pragma unroll
        for (int i = 0; i < 2; ++i) {
            int idx4 = tid + i*256;                  // < 512
            int kk = idx4 >> 5, n4 = (idx4 & 31) << 2;
            *(float4*)(Bs + kk*BSTR + n4)             = *(const float4*)(src + idx4*4);
            *(float4*)(Bs + 16*BSTR + kk*BSTR + n4)   = *(const float4*)(src + 2048 + idx4*4);
        }
        __syncthreads();

#pragma unroll
        for (int ks = 0; ks < 2; ++ks) {
            const int k0 = c*16 + ks*8;
            uint32_t Ah[2][4], Al[2][4];
#pragma unroll
            for (int mt = 0; mt < 2; ++mt) {
                const int r0 = rb + mt*16 + gid;
                float f[4];
                f[0] = As[(size_t)r0*SX + k0 + tig];
                f[1] = As[(size_t)(r0+8)*SX + k0 + tig];
                f[2] = As[(size_t)r0*SX + k0 + tig + 4];
                f[3] = As[(size_t)(r0+8)*SX + k0 + tig + 4];
#pragma unroll
                for (int i = 0; i < 4; ++i) {
                    float v = RELU ? fmaxf(f[i], 0.0f) : f[i];
                    uint32_t h = tf32_hi(v);
                    Ah[mt][i] = h;
                    Al[mt][i] = tf32_hi(v - __uint_as_float(h));
                }
            }
#pragma unroll
            for (int j = 0; j < 8; ++j) {
                const int nbase = nb + j*8 + gid;
                const float* bk0 = Bs + (ks*8 + tig)*BSTR + nbase;
                const float* bk1 = Bs + (ks*8 + tig + 4)*BSTR + nbase;
                uint32_t bh[2], bl[2];
                bh[0] = __float_as_uint(bk0[0]);
                bh[1] = __float_as_uint(bk1[0]);
                bl[0] = __float_as_uint(bk0[16*BSTR]);
                bl[1] = __float_as_uint(bk1[16*BSTR]);
#pragma unroll
                for (int mt = 0; mt < 2; ++mt) {
                    MMA_TF32(acc[mt][j], Ah[mt], bh);
                    MMA_TF32(acc[mt][j], Al[mt], bh);
                    MMA_TF32(acc[mt][j], Ah[mt], bl);
                }
            }
        }
    }
}

template<bool RELU>
__device__ __forceinline__ void store_acc_smem(float acc[2][8][4], float* tile,
                                               int rb, int nb, int lane)
{
    const int gid = lane >> 2, tig = lane & 3;
#pragma unroll
    for (int mt = 0; mt < 2; ++mt) {
        const int rg = rb + mt*16 + gid;
#pragma unroll
        for (int j = 0; j < 8; ++j) {
            const int col0 = nb + j*8 + 2*tig;
            float v0 = acc[mt][j][0], v1 = acc[mt][j][1];
            float v2 = acc[mt][j][2], v3 = acc[mt][j][3];
            if (RELU) {
                v0 = fmaxf(v0, 0.f); v1 = fmaxf(v1, 0.f);
                v2 = fmaxf(v2, 0.f); v3 = fmaxf(v3, 0.f);
            }
            *(float2*)(tile + (size_t)rg*SX + col0)     = make_float2(v0, v1);
            *(float2*)(tile + (size_t)(rg+8)*SX + col0) = make_float2(v2, v3);
        }
    }
}

__global__ __launch_bounds__(256) void resnet_tc(
    int blk,
    const float* __restrict__ b0, const float* __restrict__ b1,
    const float* __restrict__ bo, int add_res)
{
    extern __shared__ float sm[];
    float* xs  = sm;                 // [128][SX] net (x)
    float* as_ = sm + 128*SX;        // [128][SX] a1
    float* hs  = sm + 2*128*SX;      // [128][SX] att, then relu(h)
    float* Bs  = sm + 3*128*SX;      // [32][BSTR] hi+lo chunk

    const int tid = threadIdx.x;
    const int wid = tid >> 5, lane = tid & 31;
    const int rb = (wid & 3) * 32;
    const int nb = (wid >> 2) * 64;
    const int gid = lane >> 2, tig = lane & 3;
    const size_t t0 = (size_t)blockIdx.x * 128;
    const float* prep = g_bprep + (size_t)blk * 48 * 4096;

    // load net -> xs, att -> hs
    for (int q = tid; q < 128 * 32; q += 256) {
        int r = q >> 5, c = (q & 31) << 2;
        *(float4*)(xs + r * SX + c) = *(const float4*)(g_net + (t0 + r) * HH + c);
        *(float4*)(hs + r * SX + c) = *(const float4*)(g_att + (t0 + r) * HH + c);
    }

    float acc[2][8][4];

    // ---- GEMM1: a1 = att @ Wo^T + bo -> as_
    init_acc(acc, bo, nb, tig);
    gemm_tc<false>(hs, prep + 0*4096, 8, acc, Bs, tid, rb, nb);
    store_acc_smem<false>(acc, as_, rb, nb, lane);

    // ---- GEMM2: h = relu(relu([x|a1]) @ W0 + b0) -> hs
    init_acc(acc, b0, nb, tig);
    gemm_tc<true>(xs,  prep + 8*4096,  8, acc, Bs, tid, rb, nb);
    gemm_tc<true>(as_, prep + 16*4096, 8, acc, Bs, tid, rb, nb);
    __syncthreads();          // all GEMM1/2 reads of hs complete
    store_acc_smem<true>(acc, hs, rb, nb, lane);

    // ---- GEMM3+4: out = h @ W1^T + b1 + [x|a1] @ Ws^T [+ residual x]
    init_acc(acc, b1, nb, tig);
    gemm_tc<false>(hs,  prep + 24*4096, 8, acc, Bs, tid, rb, nb);
    gemm_tc<false>(xs,  prep + 32*4096, 8, acc, Bs, tid, rb, nb);
    gemm_tc<false>(as_, prep + 40*4096, 8, acc, Bs, tid, rb, nb);

#pragma unroll
    for (int mt = 0; mt < 2; ++mt) {
        const int rg = rb + mt*16 + gid;
#pragma unroll
        for (int j = 0; j < 8; ++j) {
            const int col0 = nb + j*8 + 2*tig;
            float v0 = acc[mt][j][0], v1 = acc[mt][j][1];
            float v2 = acc[mt][j][2], v3 = acc[mt][j][3];
            if (add_res) {
                float2 r0 = *(const float2*)(xs + (size_t)rg*SX + col0);
                float2 r1 = *(const float2*)(xs + (size_t)(rg+8)*SX + col0);
                v0 += r0.x; v1 += r0.y; v2 += r1.x; v3 += r1.y;
            }
            *(float2*)(g_net + (t0 + rg) * HH + col0)     = make_float2(v0, v1);
            *(float2*)(g_net + (t0 + rg + 8) * HH + col0) = make_float2(v2, v3);
        }
    }
}

// ======================= final projection (scalar, FFMA2) ===============
__device__ __forceinline__ void init_bias_f(u64 acc[8][4], const float* __restrict__ bias, int nb)
{
    ulonglong2 q0 = *(const ulonglong2*)(bias + nb);
    ulonglong2 q1 = *(const ulonglong2*)(bias + nb + 4);
#pragma unroll
    for (int r = 0; r < 8; ++r) {
        acc[r][0] = q0.x; acc[r][1] = q0.y; acc[r][2] = q1.x; acc[r][3] = q1.y;
    }
}

__global__ __launch_bounds__(256) void final_kernel(const float* __restrict__ W_c,
                                                    const float* __restrict__ b_c,
                                                    float* __restrict__ out)
{
    extern __shared__ float sm[];
    float* xs = sm;              // [128][SX]
    float* ws = sm + 128 * SX;   // [32][128]

    const int tid = threadIdx.x;
    const int tx = tid & 15;
    const int ty = tid >> 4;
    const int nb = tx * 8;
    const int rb = ty * 8;
    const size_t t0 = (size_t)blockIdx.x * 128;

    for (int q = tid; q < 128 * 32; q += 256) {
        int r = q >> 5, c = (q & 31) << 2;
        *(float4*)(xs + r * SX + c) = *(const float4*)(g_net + (t0 + r) * HH + c);
    }

    u64 acc[8][4];
    init_bias_f(acc, b_c, nb);

    for (int kt = 0; kt < 128; kt += 32) {
        __syncthreads();
        for (int q = tid; q < 1024; q += 256) {
            int kk = q >> 5, c = (q & 31) << 2;
            *(float4*)(ws + kk * 128 + c) = *(const float4*)(W_c + (size_t)(kt + kk) * 128 + c);
        }
        __syncthreads();
#pragma unroll 1
        for (int k4 = 0; k4 < 8; ++k4) {
            float4 a4[8];
#pragma unroll
            for (int r = 0; r < 8; ++r)
                a4[r] = *(const float4*)(xs + (rb + r) * SX + kt + k4 * 4);
#pragma unroll
            for (int j = 0; j < 4; ++j) {
                int kk = k4 * 4 + j;
                ulonglong2 b0v = *(const ulonglong2*)(ws + kk * 128 + nb);
                ulonglong2 b1v = *(const ulonglong2*)(ws + kk * 128 + nb + 4);
#pragma unroll
                for (int r = 0; r < 8; ++r) {
                    float a = ((const float*)&a4[r])[j];
                    u64 aa; BCAST2(aa, __float_as_uint(a));
                    FMA2(acc[r][0], aa, b0v.x, acc[r][0]);
                    FMA2(acc[r][1], aa, b0v.y, acc[r][1]);
                    FMA2(acc[r][2], aa, b1v.x, acc[r][2]);
                    FMA2(acc[r][3], aa, b1v.y, acc[r][3]);
                }
            }
        }
    }
#pragma unroll
    for (int r = 0; r < 8; ++r) {
        *(ulonglong2*)(out + (t0 + rb + r) * HH + nb)     = make_ulonglong2(acc[r][0], acc[r][1]);
        *(ulonglong2*)(out + (t0 + rb + r) * HH + nb + 4) = make_ulonglong2(acc[r][2], acc[r][3]);
    }
}

// ======================= launch =========================================
extern "C" void kernel_launch(void* const* d_in, const int* in_sizes, int n_in,
                              void* d_out, int out_size)
{
    const float* p      = (const float*)d_in[0];
    const float* W_pos  = (const float*)d_in[1];
    const float* b_pos  = (const float*)d_in[2];
    const float* blk_W0 = (const float*)d_in[3];
    const float* blk_b0 = (const float*)d_in[4];
    const float* blk_W1 = (const float*)d_in[5];
    const float* blk_b1 = (const float*)d_in[6];
    const float* blk_Ws = (const float*)d_in[7];
    const float* att_Wc = (const float*)d_in[8];
    const float* att_bc = (const float*)d_in[9];
    const float* att_Wo = (const float*)d_in[10];
    const float* att_bo = (const float*)d_in[11];
    const float* W_c    = (const float*)d_in[12];
    const float* b_c    = (const float*)d_in[13];
    float* out = (float*)d_out;

    const int RES_SMEM = (3 * 128 * SX + 32 * BSTR) * 4;   // 220,160 B
    const int FIN_SMEM = (128 * SX + 32 * 128) * 4;        //  83,968 B
    cudaFuncSetAttribute(resnet_tc,   cudaFuncAttributeMaxDynamicSharedMemorySize, RES_SMEM);
    cudaFuncSetAttribute(final_kernel, cudaFuncAttributeMaxDynamicSharedMemorySize, FIN_SMEM);

    prep_weights<<<dim3(48, NBLK), 256>>>(att_Wo, blk_W0, blk_W1, blk_Ws);
    knn_kernel<<<dim3(TT / 128, BB), 128>>>(p);
    pos_kernel<<<(BT * HH) / 256, 256>>>(p, W_pos, b_pos);

    for (int i = 0; i < NBLK; ++i) {
        attn_kernel<<<BT / 8, 256>>>(p, att_Wc + (size_t)i * 7, att_bc + i);
        resnet_tc<<<BT / 128, 256, RES_SMEM>>>(
            i, blk_b0 + (size_t)i * 128, blk_b1 + (size_t)i * 128,
            att_bo + (size_t)i * 128, i > 0 ? 1 : 0);
    }
    final_kernel<<<BT / 128, 256, FIN_SMEM>>>(W_c, b_c, out);
}